// round 2
// baseline (speedup 1.0000x reference)
#include <cuda_runtime.h>
#include <cstdint>
#include <cstddef>

#define NNODES 50000
#define NEDGES 800000
#define NTYPES 3
#define DIM    64
#define EPSLN  1e-5f

// ---------------- device scratch (static: no allocations allowed) -------------
__device__ __align__(16) float g_A[(size_t)NTYPES * NNODES * DIM];    // F@W1[:64] + b1
__device__ __align__(16) float g_B[(size_t)NTYPES * NNODES * DIM];    // F@W1[64:]
__device__ __align__(16) float g_acc[(size_t)NTYPES * NNODES * DIM];  // scatter-sum of raw p
__device__ int   g_deg[NTYPES * NNODES];                // per-type in-degree
__device__ float g_sum[NTYPES * DIM];                   // per-channel sum of p
__device__ float g_sq[NTYPES * DIM];                    // per-channel sum of p^2
__device__ float g_s[NTYPES * DIM];                     // BN scale
__device__ float g_c[NTYPES * DIM];                     // BN shift
__device__ int   g_is64;                                // edge index dtype flag

__device__ __forceinline__ float elu(float x) { return x > 0.f ? x : expm1f(x); }

// ---------------- edge-index dtype detection ----------------------------------
// If data is int64 (values < 2^31, non-negative), every odd 32-bit word is 0.
// For int32 data, odd words are random indices in [0, 50000) -> P(all zero) ~ 0.
__global__ void k_detect(const int* __restrict__ e) {
    if (threadIdx.x == 0 && blockIdx.x == 0) {
        int is64 = 1;
        for (int i = 1; i < 256; i += 2)
            if (e[i] != 0) { is64 = 0; break; }
        g_is64 = is64;
    }
}

// ---------------- zero-init ---------------------------------------------------
__global__ void k_zero() {
    size_t stride = (size_t)gridDim.x * blockDim.x;
    size_t i = (size_t)blockIdx.x * blockDim.x + threadIdx.x;
    float4 z = make_float4(0.f, 0.f, 0.f, 0.f);
    float4* a4 = reinterpret_cast<float4*>(g_acc);
    size_t n4 = (size_t)NTYPES * NNODES * DIM / 4;
    for (size_t k = i; k < n4; k += stride) a4[k] = z;
    for (size_t k = i; k < (size_t)NTYPES * NNODES; k += stride) g_deg[k] = 0;
    if (i < NTYPES * DIM) { g_sum[i] = 0.f; g_sq[i] = 0.f; }
}

// ---------------- per-node precompute: A = F@W1[:64]+b1, B = F@W1[64:] --------
__global__ void __launch_bounds__(256) k_pre(const float* __restrict__ F,
                                             const float* __restrict__ W1,
                                             const float* __restrict__ b1) {
    __shared__ float Fs[64 * 65];   // padded, node-major
    __shared__ float Ws[64 * 64];   // [k][o]
    const int tid = threadIdx.x;
    const int t = blockIdx.y;
    const int half = blockIdx.z;    // 0 -> A (src weights), 1 -> B (dst weights)

    const float* Wsrc = W1 + ((size_t)t * 128 + (size_t)half * 64) * 64;
    for (int i = tid; i < 1024; i += 256)
        reinterpret_cast<float4*>(Ws)[i] = reinterpret_cast<const float4*>(Wsrc)[i];

    const int nl = tid >> 2, q = tid & 3;
    const int n = blockIdx.x * 64 + nl;
    {
        const int nc = (n < NNODES) ? n : (NNODES - 1);   // clamp: no OOB speculation
        const float* fr = F + (size_t)nc * DIM + q * 16;
        const float mask = (n < NNODES) ? 1.f : 0.f;
#pragma unroll
        for (int i = 0; i < 16; i++)
            Fs[nl * 65 + q * 16 + i] = fr[i] * mask;
    }
    __syncthreads();

    const int ng = (tid >> 4) << 2;     // 4 nodes
    const int og = (tid & 15) << 2;     // 4 outputs
    float acc[4][4] = {};
#pragma unroll 16
    for (int k = 0; k < 64; k++) {
        float a[4];
#pragma unroll
        for (int i = 0; i < 4; i++) a[i] = Fs[(ng + i) * 65 + k];
        float4 w = *reinterpret_cast<const float4*>(&Ws[k * 64 + og]);
        const float wa[4] = {w.x, w.y, w.z, w.w};
#pragma unroll
        for (int i = 0; i < 4; i++)
#pragma unroll
            for (int j = 0; j < 4; j++) acc[i][j] += a[i] * wa[j];
    }

    float bb[4] = {0.f, 0.f, 0.f, 0.f};
    if (half == 0) {
        float4 bv = *reinterpret_cast<const float4*>(&b1[t * DIM + og]);
        bb[0] = bv.x; bb[1] = bv.y; bb[2] = bv.z; bb[3] = bv.w;
    }
    float* dst = (half ? g_B : g_A);
#pragma unroll
    for (int i = 0; i < 4; i++) {
        int nn = blockIdx.x * 64 + ng + i;
        if (nn < NNODES) {
            float4 r = make_float4(acc[i][0] + bb[0], acc[i][1] + bb[1],
                                   acc[i][2] + bb[2], acc[i][3] + bb[3]);
            *reinterpret_cast<float4*>(
                &dst[(((size_t)t * NNODES + nn) << 6) + og]) = r;
        }
    }
}

// ---------------- main edge kernel -------------------------------------------
// 64 edges per CTA. Phase A: gather A[src]+B[dst], ELU, LayerNorm (4-thread
// groups), store hn transposed. Phase B: 64x64 GEMM vs W2 (smem). Phase C:
// ELU, v4 red scatter, degree atomics, per-channel stat reduction.
__global__ void __launch_bounds__(256) k_edge(const void* __restrict__ esrc_raw,
                                              const void* __restrict__ edst_raw,
                                              const float* __restrict__ lng,
                                              const float* __restrict__ lnb,
                                              const float* __restrict__ W2,
                                              const float* __restrict__ b2) {
    __shared__ float W2s[64 * 64];
    __shared__ float hnT[64 * 72];      // [ch][edge], padded
    __shared__ float sSum[64], sSq[64];
    __shared__ int   dsts[64];
    __shared__ float s_lng[64], s_lnb[64], s_b2[64];

    const int tid = threadIdx.x;
    const int t = blockIdx.y;

    const float* W2p = W2 + (size_t)t * 64 * 64;
    for (int i = tid; i < 1024; i += 256)
        reinterpret_cast<float4*>(W2s)[i] = reinterpret_cast<const float4*>(W2p)[i];
    if (tid < 64) {
        s_lng[tid] = lng[t * DIM + tid];
        s_lnb[tid] = lnb[t * DIM + tid];
        s_b2[tid]  = b2[t * DIM + tid];
        sSum[tid] = 0.f; sSq[tid] = 0.f;
    }
    __syncthreads();   // s_lng/s_lnb consumed in phase A by all threads

    const int el = tid >> 2, q = tid & 3;
    const size_t ge = (size_t)blockIdx.x * 64 + el;
    const bool valid = ge < NEDGES;
    int src = 0, dst = 0;
    if (valid) {
        const size_t off = (size_t)t * NEDGES + ge;
        if (g_is64) {
            src = (int)((const long long*)esrc_raw)[off];
            dst = (int)((const long long*)edst_raw)[off];
        } else {
            src = ((const int*)esrc_raw)[off];
            dst = ((const int*)edst_raw)[off];
        }
    }

    float h[16];
    float sm = 0.f, sq = 0.f;
    {
        const float4* ap = reinterpret_cast<const float4*>(
            g_A + (((size_t)t * NNODES + (size_t)src) << 6) + q * 16);
        const float4* bp = reinterpret_cast<const float4*>(
            g_B + (((size_t)t * NNODES + (size_t)dst) << 6) + q * 16);
#pragma unroll
        for (int i = 0; i < 4; i++) {
            float4 a = ap[i];
            float4 b = bp[i];
            float v0 = elu(a.x + b.x), v1 = elu(a.y + b.y);
            float v2 = elu(a.z + b.z), v3 = elu(a.w + b.w);
            if (!valid) { v0 = v1 = v2 = v3 = 0.f; }
            h[i * 4 + 0] = v0; h[i * 4 + 1] = v1;
            h[i * 4 + 2] = v2; h[i * 4 + 3] = v3;
            sm += v0 + v1 + v2 + v3;
            sq += v0 * v0 + v1 * v1 + v2 * v2 + v3 * v3;
        }
    }
    // LayerNorm stats across the 4 threads of this edge
    sm += __shfl_xor_sync(0xffffffffu, sm, 1);
    sq += __shfl_xor_sync(0xffffffffu, sq, 1);
    sm += __shfl_xor_sync(0xffffffffu, sm, 2);
    sq += __shfl_xor_sync(0xffffffffu, sq, 2);
    const float mu = sm * (1.f / 64.f);
    const float var = sq * (1.f / 64.f) - mu * mu;
    const float rstd = rsqrtf(var + EPSLN);
#pragma unroll
    for (int i = 0; i < 16; i++) {
        int ch = q * 16 + i;
        hnT[ch * 72 + el] = (h[i] - mu) * rstd * s_lng[ch] + s_lnb[ch];
    }
    if (q == 0) dsts[el] = valid ? dst : -1;
    __syncthreads();

    // Phase B: P[64e x 64ch] = hn @ W2, 4x4 micro-tiles
    const int eg = (tid >> 4) << 2;
    const int og = (tid & 15) << 2;
    float acc[4][4] = {};
    const float* hp = &hnT[eg];
    const float* wp = &W2s[og];
#pragma unroll 16
    for (int m = 0; m < 64; m++) {
        float4 hv = *reinterpret_cast<const float4*>(hp); hp += 72;
        float4 wv = *reinterpret_cast<const float4*>(wp); wp += 64;
        const float ha[4] = {hv.x, hv.y, hv.z, hv.w};
        const float wa[4] = {wv.x, wv.y, wv.z, wv.w};
#pragma unroll
        for (int i = 0; i < 4; i++)
#pragma unroll
            for (int j = 0; j < 4; j++) acc[i][j] += ha[i] * wa[j];
    }

    // Phase C: ELU + scatter + stats
    float4 bv = *reinterpret_cast<const float4*>(&s_b2[og]);
    const float ba[4] = {bv.x, bv.y, bv.z, bv.w};
    float cs[4] = {0.f, 0.f, 0.f, 0.f}, cq[4] = {0.f, 0.f, 0.f, 0.f};
#pragma unroll
    for (int i = 0; i < 4; i++) {
        int d = dsts[eg + i];
        float p0 = elu(acc[i][0] + ba[0]);
        float p1 = elu(acc[i][1] + ba[1]);
        float p2 = elu(acc[i][2] + ba[2]);
        float p3 = elu(acc[i][3] + ba[3]);
        if (d >= 0) {
            float* addr = g_acc + (((size_t)t * NNODES + d) << 6) + og;
            asm volatile("red.global.add.v4.f32 [%0], {%1,%2,%3,%4};"
                         :: "l"(addr), "f"(p0), "f"(p1), "f"(p2), "f"(p3)
                         : "memory");
            cs[0] += p0; cs[1] += p1; cs[2] += p2; cs[3] += p3;
            cq[0] += p0 * p0; cq[1] += p1 * p1;
            cq[2] += p2 * p2; cq[3] += p3 * p3;
        }
    }
    if ((tid & 15) == 0) {
#pragma unroll
        for (int i = 0; i < 4; i++) {
            int d = dsts[eg + i];
            if (d >= 0) atomicAdd(&g_deg[t * NNODES + d], 1);
        }
    }
#pragma unroll
    for (int j = 0; j < 4; j++) {
        cs[j] += __shfl_xor_sync(0xffffffffu, cs[j], 16);
        cq[j] += __shfl_xor_sync(0xffffffffu, cq[j], 16);
    }
    if ((tid & 31) < 16) {
#pragma unroll
        for (int j = 0; j < 4; j++) {
            atomicAdd(&sSum[og + j], cs[j]);
            atomicAdd(&sSq[og + j], cq[j]);
        }
    }
    __syncthreads();
    if (tid < 64) {
        atomicAdd(&g_sum[t * DIM + tid], sSum[tid]);
        atomicAdd(&g_sq[t * DIM + tid], sSq[tid]);
    }
}

// ---------------- BN stats finalize -------------------------------------------
__global__ void k_stats(const float* __restrict__ bng, const float* __restrict__ bnb) {
    int i = threadIdx.x;
    if (i < NTYPES * DIM) {
        float mean = g_sum[i] * (1.f / NEDGES);
        float var = g_sq[i] * (1.f / NEDGES) - mean * mean;
        float s = bng[i] * rsqrtf(fmaxf(var, 0.f) + EPSLN);
        g_s[i] = s;
        g_c[i] = bnb[i] - mean * s;
    }
}

// ---------------- final: combine types, @Wr, +br, +features -------------------
__global__ void __launch_bounds__(256) k_final(const float* __restrict__ F,
                                               const float* __restrict__ Wr,
                                               const float* __restrict__ br,
                                               float* __restrict__ out) {
    __shared__ float Ws[64 * 64];
    __shared__ float aT[64 * 72];
    const int tid = threadIdx.x;
    for (int i = tid; i < 1024; i += 256)
        reinterpret_cast<float4*>(Ws)[i] = reinterpret_cast<const float4*>(Wr)[i];

    const int nl = tid >> 2, q = tid & 3;
    const int n = blockIdx.x * 64 + nl;
    float v[16];
#pragma unroll
    for (int i = 0; i < 16; i++) v[i] = 0.f;
    if (n < NNODES) {
#pragma unroll
        for (int t = 0; t < NTYPES; t++) {
            const float4* op = reinterpret_cast<const float4*>(
                g_acc + (((size_t)t * NNODES + n) << 6) + q * 16);
            float dg = (float)g_deg[t * NNODES + n];
#pragma unroll
            for (int i = 0; i < 4; i++) {
                float4 o = op[i];
                int ch = q * 16 + i * 4;
                v[i * 4 + 0] += o.x * g_s[t * DIM + ch + 0] + dg * g_c[t * DIM + ch + 0];
                v[i * 4 + 1] += o.y * g_s[t * DIM + ch + 1] + dg * g_c[t * DIM + ch + 1];
                v[i * 4 + 2] += o.z * g_s[t * DIM + ch + 2] + dg * g_c[t * DIM + ch + 2];
                v[i * 4 + 3] += o.w * g_s[t * DIM + ch + 3] + dg * g_c[t * DIM + ch + 3];
            }
        }
    }
#pragma unroll
    for (int i = 0; i < 16; i++) aT[(q * 16 + i) * 72 + nl] = v[i];
    __syncthreads();

    const int ng = (tid >> 4) << 2;
    const int og = (tid & 15) << 2;
    float acc[4][4] = {};
    const float* apx = &aT[ng];
    const float* wpx = &Ws[og];
#pragma unroll 16
    for (int k = 0; k < 64; k++) {
        float4 av = *reinterpret_cast<const float4*>(apx); apx += 72;
        float4 wv = *reinterpret_cast<const float4*>(wpx); wpx += 64;
        const float aa[4] = {av.x, av.y, av.z, av.w};
        const float wa[4] = {wv.x, wv.y, wv.z, wv.w};
#pragma unroll
        for (int i = 0; i < 4; i++)
#pragma unroll
            for (int j = 0; j < 4; j++) acc[i][j] += aa[i] * wa[j];
    }

    float4 brv = *reinterpret_cast<const float4*>(&br[og]);
    const float bra[4] = {brv.x, brv.y, brv.z, brv.w};
#pragma unroll
    for (int i = 0; i < 4; i++) {
        int nn = blockIdx.x * 64 + ng + i;
        if (nn < NNODES) {
            float4 f = *reinterpret_cast<const float4*>(&F[(size_t)nn * DIM + og]);
            float4 r = make_float4(acc[i][0] + bra[0] + f.x,
                                   acc[i][1] + bra[1] + f.y,
                                   acc[i][2] + bra[2] + f.z,
                                   acc[i][3] + bra[3] + f.w);
            *reinterpret_cast<float4*>(&out[(size_t)nn * DIM + og]) = r;
        }
    }
}

// ---------------- launch -------------------------------------------------------
extern "C" void kernel_launch(void* const* d_in, const int* in_sizes, int n_in,
                              void* d_out, int out_size) {
    const float* F   = (const float*)d_in[0];
    const float* W1  = (const float*)d_in[1];
    const float* b1  = (const float*)d_in[2];
    const float* lng = (const float*)d_in[3];
    const float* lnb = (const float*)d_in[4];
    const float* W2  = (const float*)d_in[5];
    const float* b2  = (const float*)d_in[6];
    const float* bng = (const float*)d_in[7];
    const float* bnb = (const float*)d_in[8];
    const float* Wr  = (const float*)d_in[9];
    const float* br  = (const float*)d_in[10];
    const void*  esrc = d_in[11];
    const void*  edst = d_in[12];

    k_detect<<<1, 32>>>((const int*)esrc);
    k_zero<<<2048, 256>>>();

    dim3 gpre((NNODES + 63) / 64, NTYPES, 2);
    k_pre<<<gpre, 256>>>(F, W1, b1);

    dim3 gedge((NEDGES + 63) / 64, NTYPES, 1);
    k_edge<<<gedge, 256>>>(esrc, edst, lng, lnb, W2, b2);

    k_stats<<<1, 256>>>(bng, bnb);

    k_final<<<(NNODES + 63) / 64, 256>>>(F, Wr, br, (float*)d_out);
}